// round 8
// baseline (speedup 1.0000x reference)
#include <cuda_runtime.h>
#include <cfloat>

#define NPTS  4096
#define MQ    1024
#define CCH   64
#define GRID  20
#define NCELL (GRID * GRID)
#define CAP   64       // points per cell; lambda=10.24, overflow prob ~1e-30
#define LCAP  256      // per-warp candidate list capacity (expect ~41 matches)
#define MAR   0.0500010f

__device__ float2 g_xy[NCELL * CAP];   // cell-sorted coords
__device__ int    g_id [NCELL * CAP];  // cell-sorted point indices
__device__ int    g_cnt[NCELL];        // per-cell counts (unclamped)

__device__ __forceinline__ int cellof(float v) {
    int c = (int)(v * 20.0f);
    return min(GRID - 1, max(0, c));
}

// ---- Pass 0: zero counts (graph replays re-run this every launch) ----
__global__ void zero_kernel() {
    g_cnt[threadIdx.x] = 0;     // exactly NCELL threads
}

// ---- Pass 1: bin all points, fully parallel (1 point / thread) ----
__global__ void bin_kernel(const float* __restrict__ coords) {
    const int i = blockIdx.x * blockDim.x + threadIdx.x;   // 4096 threads
    float2 c = ((const float2*)coords)[i];
    int cell = cellof(c.y) * GRID + cellof(c.x);
    int pos = atomicAdd(&g_cnt[cell], 1);
    if (pos < CAP) {
        g_xy[cell * CAP + pos] = c;
        g_id[cell * CAP + pos] = i;
    }
}

// ---- Pass 2: one warp per query; no block barriers, no shared atomics ----
__global__ __launch_bounds__(64)
void maxpool_query_kernel(const float* __restrict__ values,
                          const float* __restrict__ qcoords,
                          float* __restrict__ out) {
    __shared__ int s_list[2][LCAP];

    const int lane = threadIdx.x & 31;
    const int w    = threadIdx.x >> 5;           // warp within block (0..1)
    const int q    = blockIdx.x * 2 + w;         // query id

    const float2 qc = ((const float2*)qcoords)[q];
    const float qx = qc.x, qy = qc.y;

    // Candidate cell window (<=3x3). Margin absorbs float rounding at cell
    // boundaries; the exact mask test below decides membership.
    const int xlo = cellof(qx - MAR), xhi = cellof(qx + MAR);
    const int ylo = cellof(qy - MAR), yhi = cellof(qy + MAR);

    // Phase 1: warp-local candidate list via ballot + prefix (no atomics)
    int wcnt = 0;
    for (int cy = ylo; cy <= yhi; cy++) {
        for (int cx = xlo; cx <= xhi; cx++) {
            const int cell = cy * GRID + cx;
            const int cnt  = min(g_cnt[cell], CAP);
            for (int base = 0; base < cnt; base += 32) {
                const int j = base + lane;
                bool ok = false;
                int  id = 0;
                if (j < cnt) {
                    float2 c = g_xy[cell * CAP + j];
                    id = g_id[cell * CAP + j];
                    ok = (fabsf(qx - c.x) < 0.05f) & (fabsf(qy - c.y) < 0.05f);
                }
                unsigned msk = __ballot_sync(0xFFFFFFFFu, ok);
                int pos = wcnt + __popc(msk & ((1u << lane) - 1u));
                if (ok && pos < LCAP) s_list[w][pos] = id;
                wcnt += __popc(msk);
            }
        }
    }
    wcnt = min(wcnt, LCAP);
    __syncwarp();

    // Phase 2: gather-max. Each lane owns channels {2*lane, 2*lane+1};
    // one LDG.64 per row per warp = coalesced 256B. Unroll-4 for MLP.
    const float2* __restrict__ v2 = (const float2*)values;
    float m0 = -FLT_MAX, m1 = -FLT_MAX;

    int j = 0;
    for (; j + 4 <= wcnt; j += 4) {
        int i0 = s_list[w][j + 0];
        int i1 = s_list[w][j + 1];
        int i2 = s_list[w][j + 2];
        int i3 = s_list[w][j + 3];
        float2 a = v2[i0 * 32 + lane];
        float2 b = v2[i1 * 32 + lane];
        float2 c = v2[i2 * 32 + lane];
        float2 d = v2[i3 * 32 + lane];
        m0 = fmaxf(m0, fmaxf(fmaxf(a.x, b.x), fmaxf(c.x, d.x)));
        m1 = fmaxf(m1, fmaxf(fmaxf(a.y, b.y), fmaxf(c.y, d.y)));
    }
    for (; j < wcnt; j++) {
        int i0 = s_list[w][j];
        float2 a = v2[i0 * 32 + lane];
        m0 = fmaxf(m0, a.x);
        m1 = fmaxf(m1, a.y);
    }

    // Direct register -> gmem output, coalesced 256B per warp.
    ((float2*)out)[q * 32 + lane] = make_float2(m0, m1);
}

extern "C" void kernel_launch(void* const* d_in, const int* in_sizes, int n_in,
                              void* d_out, int out_size) {
    const float* values  = (const float*)d_in[0];   // [N, C] f32
    const float* coords  = (const float*)d_in[1];   // [N, 2] f32
    const float* qcoords = (const float*)d_in[2];   // [M, 2] f32
    float* out = (float*)d_out;                     // [M, C] f32

    zero_kernel<<<1, NCELL>>>();
    bin_kernel<<<NPTS / 256, 256>>>(coords);
    maxpool_query_kernel<<<MQ / 2, 64>>>(values, qcoords, out);
}

// round 9
// speedup vs baseline: 1.1000x; 1.1000x over previous
#include <cuda_runtime.h>
#include <cfloat>

#define NPTS 4096
#define MQ   1024
#define CCH  64
#define QPB  8          // queries per block (one warp each)
#define LCAP 512        // per-query candidate capacity (expect ~41, sigma ~6)

__global__ __launch_bounds__(256)
void maxpool_fused_kernel(const float* __restrict__ values,
                          const float* __restrict__ coords,
                          const float* __restrict__ qcoords,
                          float* __restrict__ out) {
    __shared__ int s_list[QPB][LCAP];
    __shared__ int s_cnt[QPB];

    const int lane = threadIdx.x & 31;
    const int w    = threadIdx.x >> 5;        // warp id in block = query slot
    const int q    = blockIdx.x * QPB + w;    // global query id

    if (lane == 0) s_cnt[w] = 0;
    __syncwarp();

    const float2 qc = ((const float2*)qcoords)[q];
    const float qx = qc.x, qy = qc.y;

    // ---- Phase 1: full coord scan, warp-private. 2 coords per lane per
    // iteration via LDG.128 (coalesced 512B per warp-iter). Matches are rare
    // (~41/4096) so the shared atomic append is predicated-off noise.
    const float4* __restrict__ c4 = (const float4*)coords;
    #pragma unroll 4
    for (int base = 0; base < NPTS / 2; base += 32) {
        float4 c = c4[base + lane];
        const int i0 = 2 * (base + lane);
        bool ok0 = (fabsf(qx - c.x) < 0.05f) & (fabsf(qy - c.y) < 0.05f);
        bool ok1 = (fabsf(qx - c.z) < 0.05f) & (fabsf(qy - c.w) < 0.05f);
        if (ok0) { int p = atomicAdd(&s_cnt[w], 1); if (p < LCAP) s_list[w][p] = i0; }
        if (ok1) { int p = atomicAdd(&s_cnt[w], 1); if (p < LCAP) s_list[w][p] = i0 + 1; }
    }
    __syncwarp();
    const int cnt = min(s_cnt[w], LCAP);

    // ---- Phase 2: gather-max. Lane owns channels {2*lane, 2*lane+1};
    // one float2 per row per lane -> coalesced 256B per warp. Unroll-4 MLP.
    const float2* __restrict__ v2 = (const float2*)values;
    float m0 = -FLT_MAX, m1 = -FLT_MAX;

    int j = 0;
    for (; j + 4 <= cnt; j += 4) {
        int i0 = s_list[w][j + 0];
        int i1 = s_list[w][j + 1];
        int i2 = s_list[w][j + 2];
        int i3 = s_list[w][j + 3];
        float2 a = v2[i0 * 32 + lane];
        float2 b = v2[i1 * 32 + lane];
        float2 c = v2[i2 * 32 + lane];
        float2 d = v2[i3 * 32 + lane];
        m0 = fmaxf(m0, fmaxf(fmaxf(a.x, b.x), fmaxf(c.x, d.x)));
        m1 = fmaxf(m1, fmaxf(fmaxf(a.y, b.y), fmaxf(c.y, d.y)));
    }
    for (; j < cnt; j++) {
        int i0 = s_list[w][j];
        float2 a = v2[i0 * 32 + lane];
        m0 = fmaxf(m0, a.x);
        m1 = fmaxf(m1, a.y);
    }

    // Direct register -> gmem output, coalesced 256B per warp.
    ((float2*)out)[q * 32 + lane] = make_float2(m0, m1);
}

extern "C" void kernel_launch(void* const* d_in, const int* in_sizes, int n_in,
                              void* d_out, int out_size) {
    const float* values  = (const float*)d_in[0];   // [N, C] f32
    const float* coords  = (const float*)d_in[1];   // [N, 2] f32
    const float* qcoords = (const float*)d_in[2];   // [M, 2] f32
    float* out = (float*)d_out;                     // [M, C] f32

    maxpool_fused_kernel<<<MQ / QPB, 256>>>(values, coords, qcoords, out);
}

// round 10
// speedup vs baseline: 1.6656x; 1.5142x over previous
#include <cuda_runtime.h>
#include <cfloat>

#define NPTS 4096
#define MQ   1024
#define CCH  64
#define LCAP 512        // candidate capacity (expect ~41, sigma ~6)

__global__ __launch_bounds__(256)
void maxpool_fused_kernel(const float* __restrict__ values,
                          const float* __restrict__ coords,
                          const float* __restrict__ qcoords,
                          float* __restrict__ out) {
    __shared__ int   s_list[LCAP];
    __shared__ int   s_cnt;
    __shared__ float s_part[8][CCH];

    const int tid  = threadIdx.x;
    const int lane = tid & 31;
    const int w    = tid >> 5;               // warp 0..7
    const int q    = blockIdx.x;             // one block per query

    if (tid == 0) s_cnt = 0;
    __syncthreads();

    const float2 qc = ((const float2*)qcoords)[q];
    const float qx = qc.x, qy = qc.y;

    // ---- Phase 1: brute-force scan, block-wide. Each thread tests 16 points
    // as 8 float4 loads (2 pts each), fully unrolled -> deep MLP. Appends are
    // rare (~41/4096) so the shared atomicAdd is predicated-off noise.
    const float4* __restrict__ c4 = (const float4*)coords;
    #pragma unroll
    for (int it = 0; it < 8; it++) {
        const int v = it * 256 + tid;        // float4 index (2 points)
        float4 c = c4[v];
        const int i0 = 2 * v;
        bool ok0 = (fabsf(qx - c.x) < 0.05f) & (fabsf(qy - c.y) < 0.05f);
        bool ok1 = (fabsf(qx - c.z) < 0.05f) & (fabsf(qy - c.w) < 0.05f);
        if (ok0) { int p = atomicAdd(&s_cnt, 1); if (p < LCAP) s_list[p] = i0; }
        if (ok1) { int p = atomicAdd(&s_cnt, 1); if (p < LCAP) s_list[p] = i0 + 1; }
    }
    __syncthreads();
    const int cnt = min(s_cnt, LCAP);

    // ---- Phase 2: gather-max. 8 warp-slices over candidates; lane owns
    // channels {2*lane, 2*lane+1} -> one coalesced 256B float2 row per warp.
    const float2* __restrict__ v2 = (const float2*)values;
    float m0 = -FLT_MAX, m1 = -FLT_MAX;

    int j = w;
    for (; j + 32 <= cnt; j += 32) {         // unroll-4 over warp-slices
        int i0 = s_list[j +  0];
        int i1 = s_list[j +  8];
        int i2 = s_list[j + 16];
        int i3 = s_list[j + 24];
        float2 a = v2[i0 * 32 + lane];
        float2 b = v2[i1 * 32 + lane];
        float2 c = v2[i2 * 32 + lane];
        float2 d = v2[i3 * 32 + lane];
        m0 = fmaxf(m0, fmaxf(fmaxf(a.x, b.x), fmaxf(c.x, d.x)));
        m1 = fmaxf(m1, fmaxf(fmaxf(a.y, b.y), fmaxf(c.y, d.y)));
    }
    for (; j < cnt; j += 8) {
        int i0 = s_list[j];
        float2 a = v2[i0 * 32 + lane];
        m0 = fmaxf(m0, a.x);
        m1 = fmaxf(m1, a.y);
    }

    s_part[w][2 * lane]     = m0;
    s_part[w][2 * lane + 1] = m1;
    __syncthreads();

    // ---- Final reduce across the 8 warp-slices; coalesced 256B store.
    if (tid < CCH) {
        float r = s_part[0][tid];
        #pragma unroll
        for (int k = 1; k < 8; k++) r = fmaxf(r, s_part[k][tid]);
        out[q * CCH + tid] = r;
    }
}

extern "C" void kernel_launch(void* const* d_in, const int* in_sizes, int n_in,
                              void* d_out, int out_size) {
    const float* values  = (const float*)d_in[0];   // [N, C] f32
    const float* coords  = (const float*)d_in[1];   // [N, 2] f32
    const float* qcoords = (const float*)d_in[2];   // [M, 2] f32
    float* out = (float*)d_out;                     // [M, C] f32

    maxpool_fused_kernel<<<MQ, 256>>>(values, coords, qcoords, out);
}

// round 11
// speedup vs baseline: 1.8857x; 1.1321x over previous
#include <cuda_runtime.h>
#include <cfloat>

#define NPTS 4096
#define MQ   1024
#define CCH  64
#define LCAP 512        // candidate capacity (expect ~41, sigma ~6)

__global__ __launch_bounds__(256)
void maxpool_fused_kernel(const float* __restrict__ values,
                          const float* __restrict__ coords,
                          const float* __restrict__ qcoords,
                          float* __restrict__ out) {
    __shared__ int   s_list[LCAP];
    __shared__ int   s_cnt;
    __shared__ float s_part[8][CCH];

    const int tid  = threadIdx.x;
    const int lane = tid & 31;
    const int w    = tid >> 5;               // warp 0..7
    const int q    = blockIdx.x;             // one block per query

    if (tid == 0) s_cnt = 0;
    __syncthreads();

    const float2 qc = ((const float2*)qcoords)[q];
    const float qx = qc.x, qy = qc.y;

    // Packed (-qx,-qy) for one-instruction f32x2 subtract per point.
    unsigned long long nq;
    asm("mov.b64 %0, {%1, %2};" : "=l"(nq) : "f"(-qx), "f"(-qy));

    // ---- Phase 1: branch-free scan. Each thread tests 16 points (8 x LDG.128,
    // 2 points each); results go into a 16-bit register mask via predicated
    // LOP3 -- zero branches in the hot loop, so all 8 loads batch for MLP.
    const float4* __restrict__ c4 = (const float4*)coords;
    unsigned mmask = 0;
    #pragma unroll
    for (int it = 0; it < 8; it++) {
        float4 c = c4[it * 256 + tid];
        unsigned long long p0, p1, d0, d1;
        asm("mov.b64 %0, {%1, %2};" : "=l"(p0) : "f"(c.x), "f"(c.y));
        asm("mov.b64 %0, {%1, %2};" : "=l"(p1) : "f"(c.z), "f"(c.w));
        asm("add.rn.f32x2 %0, %1, %2;" : "=l"(d0) : "l"(p0), "l"(nq));
        asm("add.rn.f32x2 %0, %1, %2;" : "=l"(d1) : "l"(p1), "l"(nq));
        float dx0, dy0, dx1, dy1;
        asm("mov.b64 {%0, %1}, %2;" : "=f"(dx0), "=f"(dy0) : "l"(d0));
        asm("mov.b64 {%0, %1}, %2;" : "=f"(dx1), "=f"(dy1) : "l"(d1));
        if (fmaxf(fabsf(dx0), fabsf(dy0)) < 0.05f) mmask |= 1u << (2 * it);
        if (fmaxf(fabsf(dx1), fabsf(dy1)) < 0.05f) mmask |= 2u << (2 * it);
    }

    // Push matches (expected 0.16/thread; ~87% of threads skip entirely).
    while (mmask) {
        int b = __ffs(mmask) - 1;
        mmask &= mmask - 1;
        int idx = 2 * ((b >> 1) * 256 + tid) + (b & 1);
        int p = atomicAdd(&s_cnt, 1);
        if (p < LCAP) s_list[p] = idx;
    }
    __syncthreads();
    const int cnt = min(s_cnt, LCAP);

    // ---- Phase 2: gather-max. 8 warp-slices over candidates; lane owns
    // channels {2*lane, 2*lane+1} -> one coalesced 256B float2 row per warp.
    const float2* __restrict__ v2 = (const float2*)values;
    float m0 = -FLT_MAX, m1 = -FLT_MAX;

    int j = w;
    for (; j + 32 <= cnt; j += 32) {         // unroll-4 over warp-slices
        int i0 = s_list[j +  0];
        int i1 = s_list[j +  8];
        int i2 = s_list[j + 16];
        int i3 = s_list[j + 24];
        float2 a = v2[i0 * 32 + lane];
        float2 b = v2[i1 * 32 + lane];
        float2 c = v2[i2 * 32 + lane];
        float2 d = v2[i3 * 32 + lane];
        m0 = fmaxf(m0, fmaxf(fmaxf(a.x, b.x), fmaxf(c.x, d.x)));
        m1 = fmaxf(m1, fmaxf(fmaxf(a.y, b.y), fmaxf(c.y, d.y)));
    }
    for (; j < cnt; j += 8) {
        int i0 = s_list[j];
        float2 a = v2[i0 * 32 + lane];
        m0 = fmaxf(m0, a.x);
        m1 = fmaxf(m1, a.y);
    }

    s_part[w][2 * lane]     = m0;
    s_part[w][2 * lane + 1] = m1;
    __syncthreads();

    // ---- Final reduce across the 8 warp-slices; coalesced 256B store.
    if (tid < CCH) {
        float r = s_part[0][tid];
        #pragma unroll
        for (int k = 1; k < 8; k++) r = fmaxf(r, s_part[k][tid]);
        out[q * CCH + tid] = r;
    }
}

extern "C" void kernel_launch(void* const* d_in, const int* in_sizes, int n_in,
                              void* d_out, int out_size) {
    const float* values  = (const float*)d_in[0];   // [N, C] f32
    const float* coords  = (const float*)d_in[1];   // [N, 2] f32
    const float* qcoords = (const float*)d_in[2];   // [M, 2] f32
    float* out = (float*)d_out;                     // [M, C] f32

    maxpool_fused_kernel<<<MQ, 256>>>(values, coords, qcoords, out);
}